// round 1
// baseline (speedup 1.0000x reference)
#include <cuda_runtime.h>

// Problem constants (fixed by the dataset)
constexpr int B = 2, H = 16, S = 2048, D = 64;
constexpr float INV_T = 1.0f / 32.0f;   // 1/TEMPERATURE

constexpr int QT = 16;     // query rows per block
constexpr int KT = 128;    // key/value rows per SMEM tile
constexpr int THREADS = 256;
constexpr int SST = S + 1;  // score row stride (2049) -> conflict-free
constexpr int KST = D + 4;  // K/V row stride (68)     -> f4-aligned, conflict-free

// SMEM layout (floats): Q tile | K/V tile | scores | reduction pad | inv_l
constexpr int SM_Q   = 0;
constexpr int SM_K   = SM_Q + QT * D;          // 1024
constexpr int SM_S   = SM_K + KT * KST;        // +8704
constexpr int SM_RED = SM_S + QT * SST;        // +32784
constexpr int SM_INV = SM_RED + QT * 17;       // +272
constexpr int SM_FLOATS = SM_INV + QT;         // +16  = 42800 floats
constexpr int SMEM_BYTES = SM_FLOATS * 4;      // 171200 B

__global__ __launch_bounds__(THREADS, 1)
void attn_kernel(const float* __restrict__ q,
                 const float* __restrict__ k,
                 const float* __restrict__ v,
                 const int*   __restrict__ mask,
                 float* __restrict__ out,
                 float* __restrict__ attn)
{
    extern __shared__ float sm[];
    float* sQ   = sm + SM_Q;
    float* sKV  = sm + SM_K;
    float* sS   = sm + SM_S;
    float* sRed = sm + SM_RED;
    float* sInv = sm + SM_INV;

    const int t  = threadIdx.x;
    const int bh = blockIdx.y;           // 0..31
    const int b  = bh / H;
    const int q0 = blockIdx.x * QT;

    const float* qp = q + ((size_t)bh * S + q0) * D;
    const float* kp = k + (size_t)bh * S * D;
    const float* vp = v + (size_t)bh * S * D;
    const int*   mp = mask + (size_t)b * S;

    // ---- load Q tile (pre-scaled by 1/T), coalesced float4 ----
    {
        const float4* qsrc = (const float4*)qp;
        for (int i = t; i < QT * D / 4; i += THREADS) {
            float4 val = qsrc[i];
            val.x *= INV_T; val.y *= INV_T; val.z *= INV_T; val.w *= INV_T;
            ((float4*)sQ)[i] = val;
        }
    }
    __syncthreads();

    const int qi    = t & 15;   // query row this thread owns
    const int kslot = t >> 4;   // 0..15

    // Q row in registers (64 floats)
    float4 qr[16];
#pragma unroll
    for (int i = 0; i < 16; i++)
        qr[i] = *(const float4*)(sQ + qi * D + i * 4);

    // ================= QK^T : fill sS[qi][0..S) =================
    for (int kt = 0; kt < S / KT; kt++) {
        __syncthreads();   // previous tile's consumers done
        // load K tile -> sKV (padded rows)
        const float4* ksrc = (const float4*)(kp + (size_t)kt * KT * D);
        for (int i = t; i < KT * D / 4; i += THREADS) {
            int row = i >> 4;          // 16 float4 per row
            int c4  = i & 15;
            *(float4*)(sKV + row * KST + c4 * 4) = ksrc[i];
        }
        __syncthreads();

#pragma unroll
        for (int jj = 0; jj < 8; jj++) {
            int j = kslot * 8 + jj;
            const float* kr = sKV + j * KST;
            float acc = 0.0f;
#pragma unroll
            for (int d4 = 0; d4 < 16; d4++) {
                float4 kv = *(const float4*)(kr + d4 * 4);
                acc += qr[d4].x * kv.x;
                acc += qr[d4].y * kv.y;
                acc += qr[d4].z * kv.z;
                acc += qr[d4].w * kv.w;
            }
            int jg = kt * KT + j;
            if (mp[jg] == 0) acc = -1e9f;
            sS[qi * SST + jg] = acc;
        }
    }
    __syncthreads();

    // ================= softmax over each of 16 rows =================
    {
        const int r  = t >> 4;   // row handled by this 16-thread group
        const int li = t & 15;

        float m = -3.402823466e38f;
        for (int c = li; c < S; c += 16)
            m = fmaxf(m, sS[r * SST + c]);
        sRed[r * 17 + li] = m;
        __syncthreads();
        if (li == 0) {
            float mm = sRed[r * 17];
#pragma unroll
            for (int i = 1; i < 16; i++) mm = fmaxf(mm, sRed[r * 17 + i]);
            sRed[r * 17 + 16] = mm;
        }
        __syncthreads();
        const float mm = sRed[r * 17 + 16];

        float lsum = 0.0f;
        for (int c = li; c < S; c += 16) {
            float e = __expf(sS[r * SST + c] - mm);
            sS[r * SST + c] = e;
            lsum += e;
        }
        __syncthreads();
        sRed[r * 17 + li] = lsum;
        __syncthreads();
        if (li == 0) {
            float l = 0.0f;
#pragma unroll
            for (int i = 0; i < 16; i++) l += sRed[r * 17 + i];
            sInv[r] = 1.0f / l;
        }
        __syncthreads();
    }

    // ================= write attention = e * inv_l =================
    {
        for (int idx = t; idx < QT * S; idx += THREADS) {
            int rr = idx >> 11;        // /2048
            int cc = idx & (S - 1);
            attn[((size_t)bh * S + q0 + rr) * S + cc] = sS[rr * SST + cc] * sInv[rr];
        }
    }

    // ================= AV : out[qi][d..d+3] =================
    {
        const int dslot = t >> 4;
        const int d = dslot * 4;
        float4 acc = make_float4(0.f, 0.f, 0.f, 0.f);

        for (int kt = 0; kt < S / KT; kt++) {
            __syncthreads();   // previous tile's consumers done
            const float4* vsrc = (const float4*)(vp + (size_t)kt * KT * D);
            for (int i = t; i < KT * D / 4; i += THREADS) {
                int row = i >> 4;
                int c4  = i & 15;
                *(float4*)(sKV + row * KST + c4 * 4) = vsrc[i];
            }
            __syncthreads();

            const float* srow = sS + qi * SST + kt * KT;
#pragma unroll 4
            for (int j = 0; j < KT; j++) {
                float a = srow[j];
                float4 vv = *(const float4*)(sKV + j * KST + d);
                acc.x += a * vv.x;
                acc.y += a * vv.y;
                acc.z += a * vv.z;
                acc.w += a * vv.w;
            }
        }

        const float inv = sInv[qi];
        acc.x *= inv; acc.y *= inv; acc.z *= inv; acc.w *= inv;
        *(float4*)(out + ((size_t)bh * S + q0 + qi) * D + d) = acc;
    }
}

extern "C" void kernel_launch(void* const* d_in, const int* in_sizes, int n_in,
                              void* d_out, int out_size)
{
    const float* q    = (const float*)d_in[0];
    const float* k    = (const float*)d_in[1];
    const float* v    = (const float*)d_in[2];
    const int*   mask = (const int*)  d_in[3];

    float* out  = (float*)d_out;
    float* attn = out + (size_t)B * H * S * D;   // attention follows output

    cudaFuncSetAttribute(attn_kernel,
                         cudaFuncAttributeMaxDynamicSharedMemorySize, SMEM_BYTES);

    dim3 grid(S / QT, B * H);
    attn_kernel<<<grid, THREADS, SMEM_BYTES>>>(q, k, v, mask, out, attn);
}

// round 3
// speedup vs baseline: 7.3255x; 7.3255x over previous
#include <cuda_runtime.h>
#include <cuda_fp16.h>
#include <stdint.h>

// ---------------- problem constants ----------------
constexpr int B = 2, H = 16, S = 2048, D = 64;
constexpr int BH = B * H;
constexpr float INV_T = 1.0f / 32.0f;

constexpr int QT = 128;           // query rows per CTA
constexpr int NT = 128;           // keys per tile
constexpr int NTILES = S / NT;    // 16
constexpr int THREADS = 256;      // 8 warps, warp w owns q-rows 16w..16w+15

// smem tile geometry: rows of 64 fp16 padded to 72 (144B) -> conflict-free ldmatrix
constexpr int RS  = 72;
constexpr int RSB = 144;
constexpr int TILE_BYTES = 128 * RSB;   // 18432

// smem offsets (bytes)
constexpr int SM_Q    = 0;
constexpr int SM_K0   = SM_Q  + TILE_BYTES;
constexpr int SM_K1   = SM_K0 + TILE_BYTES;
constexpr int SM_V0   = SM_K1 + TILE_BYTES;
constexpr int SM_V1   = SM_V0 + TILE_BYTES;
constexpr int SM_MASK = SM_V1 + TILE_BYTES;   // 2048 floats
constexpr int SMEM_SZ = SM_MASK + S * 4;      // 100352 B

// ---------------- device fp16 copies (prep kernel fills) ----------------
__device__ __half g_q16[(size_t)BH * S * D];
__device__ __half g_k16[(size_t)BH * S * D];
__device__ __half g_v16[(size_t)BH * S * D];

// ---------------- helpers ----------------
__device__ __forceinline__ uint32_t su32(const void* p) {
    uint32_t a;
    asm("{ .reg .u64 t; cvta.to.shared.u64 t, %1; cvt.u32.u64 %0, t; }" : "=r"(a) : "l"(p));
    return a;
}
__device__ __forceinline__ void cpa16(uint32_t d, const void* s) {
    asm volatile("cp.async.cg.shared.global [%0], [%1], 16;" :: "r"(d), "l"(s));
}
#define CP_COMMIT() asm volatile("cp.async.commit_group;" ::: "memory")
#define CP_WAIT0()  asm volatile("cp.async.wait_group 0;" ::: "memory")

#define LDSM4(r0, r1, r2, r3, a) \
    asm volatile("ldmatrix.sync.aligned.m8n8.x4.shared.b16 {%0,%1,%2,%3}, [%4];" \
                 : "=r"(r0), "=r"(r1), "=r"(r2), "=r"(r3) : "r"(a))
#define LDSM4T(r0, r1, r2, r3, a) \
    asm volatile("ldmatrix.sync.aligned.m8n8.x4.trans.shared.b16 {%0,%1,%2,%3}, [%4];" \
                 : "=r"(r0), "=r"(r1), "=r"(r2), "=r"(r3) : "r"(a))

__device__ __forceinline__ void mma_f16(float4& c, uint32_t a0, uint32_t a1,
                                        uint32_t a2, uint32_t a3,
                                        uint32_t b0, uint32_t b1) {
    asm volatile(
        "mma.sync.aligned.m16n8k16.row.col.f32.f16.f16.f32 "
        "{%0,%1,%2,%3}, {%4,%5,%6,%7}, {%8,%9}, {%0,%1,%2,%3};"
        : "+f"(c.x), "+f"(c.y), "+f"(c.z), "+f"(c.w)
        : "r"(a0), "r"(a1), "r"(a2), "r"(a3), "r"(b0), "r"(b1));
}

__device__ __forceinline__ uint32_t packh2(float a, float b) {
    __half2 h = __floats2half2_rn(a, b);   // a -> low half (a0), b -> high (a1)
    return *(uint32_t*)&h;
}

// bring one 128x64 fp16 tile into padded smem via cp.async
__device__ __forceinline__ void load_tile(uint32_t sdst, const __half* g, int tid) {
#pragma unroll
    for (int it = 0; it < 4; it++) {
        int f = tid + it * THREADS;     // 0..1023
        int r = f >> 3, c = f & 7;
        cpa16(sdst + r * RSB + c * 16, g + r * 64 + c * 8);
    }
}

// ---------------- prep: fp32 -> fp16 (Q scaled by 1/T) ----------------
__global__ void prep16(const float* __restrict__ q, const float* __restrict__ k,
                       const float* __restrict__ v) {
    const int N4 = BH * S * D / 4;
    int i = blockIdx.x * blockDim.x + threadIdx.x;
    if (i >= N4) return;
    float4 a = ((const float4*)q)[i];
    float4 b = ((const float4*)k)[i];
    float4 c = ((const float4*)v)[i];
    __half2* q2 = (__half2*)g_q16;
    __half2* k2 = (__half2*)g_k16;
    __half2* v2 = (__half2*)g_v16;
    q2[2 * i]     = __floats2half2_rn(a.x * INV_T, a.y * INV_T);
    q2[2 * i + 1] = __floats2half2_rn(a.z * INV_T, a.w * INV_T);
    k2[2 * i]     = __floats2half2_rn(b.x, b.y);
    k2[2 * i + 1] = __floats2half2_rn(b.z, b.w);
    v2[2 * i]     = __floats2half2_rn(c.x, c.y);
    v2[2 * i + 1] = __floats2half2_rn(c.z, c.w);
}

// ---------------- main fused attention ----------------
__global__ __launch_bounds__(THREADS, 1)
void attn_main(const int* __restrict__ mask,
               float* __restrict__ out, float* __restrict__ attn)
{
    extern __shared__ char smem[];
    const uint32_t sb = su32(smem);
    const int tid = threadIdx.x;
    const int w   = tid >> 5;
    const int L   = tid & 31;
    const int bh  = blockIdx.y;
    const int q0  = blockIdx.x * QT;

    const __half* qg = g_q16 + ((size_t)bh * S + q0) * D;
    const __half* kg = g_k16 + (size_t)bh * S * D;
    const __half* vg = g_v16 + (size_t)bh * S * D;

    const uint32_t sQ = sb + SM_Q;
    const uint32_t sK[2] = { sb + SM_K0, sb + SM_K1 };
    const uint32_t sV[2] = { sb + SM_V0, sb + SM_V1 };
    float* mf = (float*)(smem + SM_MASK);

    // prologue: Q + K0 tiles, mask->float
    load_tile(sQ, qg, tid);
    load_tile(sK[0], kg, tid);
    CP_COMMIT();
    {
        const int* mp = mask + (size_t)(bh >> 4) * S;   // b = bh / H
        for (int i = tid; i < S; i += THREADS) mf[i] = mp[i] ? 1.0f : 0.0f;
    }
    CP_WAIT0();
    __syncthreads();

    // per-lane ldmatrix address parts
    const uint32_t q_part  = ((L & 7) + ((L >> 3) & 1) * 8) * RSB + (L >> 4) * 16;
    const uint32_t qbase   = sQ + w * 16 * RSB + q_part;
    const uint32_t ka_part = (L & 7) * RSB + (L >> 3) * 16;   // row=8nb+(L&7), col=32ks2+8(L>>3)
    const uint32_t va_part = L * RSB;                          // row=32kb2+L, col=8nb

    // Q fragments (persist whole kernel): qa[ks][0..3]
    uint32_t qa[4][4];
#pragma unroll
    for (int ks = 0; ks < 4; ks++)
        LDSM4(qa[ks][0], qa[ks][1], qa[ks][2], qa[ks][3], qbase + ks * 32);

    const int   c_base = 2 * (L & 3);
    float sum_lo = 0.0f, sum_hi = 0.0f;

    // ================= pass 1: row sums =================
    for (int kt = 0; kt < NTILES; kt++) {
        const int cur = kt & 1;
        if (kt + 1 < NTILES) { load_tile(sK[cur ^ 1], kg + (size_t)(kt + 1) * NT * D, tid); CP_COMMIT(); }

        float4 cf[16];
#pragma unroll
        for (int nb = 0; nb < 16; nb++) cf[nb] = make_float4(0.f, 0.f, 0.f, 0.f);

#pragma unroll
        for (int nb = 0; nb < 16; nb++) {
            uint32_t kaddr = sK[cur] + nb * 8 * RSB + ka_part;
            uint32_t b0, b1, b2, b3, b4, b5, b6, b7;
            LDSM4(b0, b1, b2, b3, kaddr);        // ks0, ks1
            LDSM4(b4, b5, b6, b7, kaddr + 64);   // ks2, ks3
            mma_f16(cf[nb], qa[0][0], qa[0][1], qa[0][2], qa[0][3], b0, b1);
            mma_f16(cf[nb], qa[1][0], qa[1][1], qa[1][2], qa[1][3], b2, b3);
            mma_f16(cf[nb], qa[2][0], qa[2][1], qa[2][2], qa[2][3], b4, b5);
            mma_f16(cf[nb], qa[3][0], qa[3][1], qa[3][2], qa[3][3], b6, b7);
        }

        const float* mrow = mf + kt * NT;
#pragma unroll
        for (int nb = 0; nb < 16; nb++) {
            int c0 = nb * 8 + c_base;
            float m0 = mrow[c0], m1 = mrow[c0 + 1];
            sum_lo += m0 * __expf(cf[nb].x) + m1 * __expf(cf[nb].y);
            sum_hi += m0 * __expf(cf[nb].z) + m1 * __expf(cf[nb].w);
        }

        if (kt + 1 < NTILES) CP_WAIT0();
        __syncthreads();
    }

    // quad reduction -> full row sums on every lane
#pragma unroll
    for (int m = 1; m < 4; m <<= 1) {
        sum_lo += __shfl_xor_sync(0xffffffffu, sum_lo, m);
        sum_hi += __shfl_xor_sync(0xffffffffu, sum_hi, m);
    }
    const float inv_lo = 1.0f / sum_lo;
    const float inv_hi = 1.0f / sum_hi;

    // ================= pass 2: attn write + PV =================
    load_tile(sK[0], kg, tid);
    load_tile(sV[0], vg, tid);
    CP_COMMIT();
    CP_WAIT0();
    __syncthreads();

    float4 oc[8];
#pragma unroll
    for (int nb = 0; nb < 8; nb++) oc[nb] = make_float4(0.f, 0.f, 0.f, 0.f);

    float* alo = attn + ((size_t)bh * S + q0 + w * 16 + (L >> 2)) * S;
    float* ahi = alo + 8 * (size_t)S;

    for (int kt = 0; kt < NTILES; kt++) {
        const int cur = kt & 1;
        if (kt + 1 < NTILES) {
            load_tile(sK[cur ^ 1], kg + (size_t)(kt + 1) * NT * D, tid);
            load_tile(sV[cur ^ 1], vg + (size_t)(kt + 1) * NT * D, tid);
            CP_COMMIT();
        }

        // ---- QK^T ----
        float4 cf[16];
#pragma unroll
        for (int nb = 0; nb < 16; nb++) cf[nb] = make_float4(0.f, 0.f, 0.f, 0.f);
#pragma unroll
        for (int nb = 0; nb < 16; nb++) {
            uint32_t kaddr = sK[cur] + nb * 8 * RSB + ka_part;
            uint32_t b0, b1, b2, b3, b4, b5, b6, b7;
            LDSM4(b0, b1, b2, b3, kaddr);
            LDSM4(b4, b5, b6, b7, kaddr + 64);
            mma_f16(cf[nb], qa[0][0], qa[0][1], qa[0][2], qa[0][3], b0, b1);
            mma_f16(cf[nb], qa[1][0], qa[1][1], qa[1][2], qa[1][3], b2, b3);
            mma_f16(cf[nb], qa[2][0], qa[2][1], qa[2][2], qa[2][3], b4, b5);
            mma_f16(cf[nb], qa[3][0], qa[3][1], qa[3][2], qa[3][3], b6, b7);
        }

        // ---- epilogue: p = exp(s)*inv*mask ; STG attn ; pack fp16 A-frags ----
        const float* mrow = mf + kt * NT;
        uint32_t a16[8][4];
#pragma unroll
        for (int nb = 0; nb < 16; nb++) {
            int c0 = nb * 8 + c_base;
            float m0 = mrow[c0], m1 = mrow[c0 + 1];
            float p0 = __expf(cf[nb].x) * inv_lo * m0;
            float p1 = __expf(cf[nb].y) * inv_lo * m1;
            float p2 = __expf(cf[nb].z) * inv_hi * m0;
            float p3 = __expf(cf[nb].w) * inv_hi * m1;
            *(float2*)(alo + kt * NT + c0) = make_float2(p0, p1);
            *(float2*)(ahi + kt * NT + c0) = make_float2(p2, p3);
            int kb = nb >> 1, hi2 = (nb & 1) * 2;
            a16[kb][hi2]     = packh2(p0, p1);
            a16[kb][hi2 + 1] = packh2(p2, p3);
        }

        // ---- PV: out += P(16x128) * V(128x64) ----
#pragma unroll
        for (int nb = 0; nb < 8; nb++) {
#pragma unroll
            for (int kb2 = 0; kb2 < 4; kb2++) {
                uint32_t vaddr = sV[cur] + kb2 * 32 * RSB + nb * 16 + va_part;
                uint32_t v0, v1, v2, v3;
                LDSM4T(v0, v1, v2, v3, vaddr);
                int kb = 2 * kb2;
                mma_f16(oc[nb], a16[kb][0], a16[kb][1], a16[kb][2], a16[kb][3], v0, v1);
                mma_f16(oc[nb], a16[kb + 1][0], a16[kb + 1][1], a16[kb + 1][2], a16[kb + 1][3], v2, v3);
            }
        }

        if (kt + 1 < NTILES) CP_WAIT0();
        __syncthreads();
    }

    // ---- output write ----
    float* olo = out + ((size_t)bh * S + q0 + w * 16 + (L >> 2)) * D + c_base;
    float* ohi = olo + 8 * D;
#pragma unroll
    for (int nb = 0; nb < 8; nb++) {
        *(float2*)(olo + nb * 8) = make_float2(oc[nb].x, oc[nb].y);
        *(float2*)(ohi + nb * 8) = make_float2(oc[nb].z, oc[nb].w);
    }
}

// ---------------- launch ----------------
extern "C" void kernel_launch(void* const* d_in, const int* in_sizes, int n_in,
                              void* d_out, int out_size)
{
    const float* q    = (const float*)d_in[0];
    const float* k    = (const float*)d_in[1];
    const float* v    = (const float*)d_in[2];
    const int*   mask = (const int*)  d_in[3];

    float* out  = (float*)d_out;
    float* attn = out + (size_t)BH * S * D;

    cudaFuncSetAttribute(attn_main, cudaFuncAttributeMaxDynamicSharedMemorySize, SMEM_SZ);

    const int N4 = BH * S * D / 4;
    prep16<<<(N4 + 255) / 256, 256>>>(q, k, v);
    attn_main<<<dim3(S / QT, BH), THREADS, SMEM_SZ>>>(mask, out, attn);
}

// round 4
// speedup vs baseline: 7.6800x; 1.0484x over previous
#include <cuda_runtime.h>
#include <cuda_fp16.h>
#include <stdint.h>

// ---------------- problem constants ----------------
constexpr int B = 2, H = 16, S = 2048, D = 64;
constexpr int BH = B * H;
constexpr float INV_T = 1.0f / 32.0f;

constexpr int QT = 64;            // query rows per CTA
constexpr int NT = 128;           // keys per tile
constexpr int NTILES = S / NT;    // 16
constexpr int THREADS = 128;      // 4 warps, warp w owns q-rows 16w..16w+15
constexpr int NW = 4;
constexpr int NCTA = (S / QT) * BH;  // 1024

// smem tile geometry: rows of 64 fp16 padded to 72 (144B) -> conflict-free ldmatrix
constexpr int RSB = 144;
constexpr int QTILE_BYTES = 64 * RSB;    // 9216
constexpr int KTILE_BYTES = 128 * RSB;   // 18432

constexpr int SM_Q    = 0;
constexpr int SM_K0   = SM_Q  + QTILE_BYTES;
constexpr int SM_K1   = SM_K0 + KTILE_BYTES;
constexpr int SM_V0   = SM_K1 + KTILE_BYTES;
constexpr int SM_V1   = SM_V0 + KTILE_BYTES;
constexpr int SM_MASK = SM_V1 + KTILE_BYTES;
constexpr int SMEM_SZ = SM_MASK + S * 4;      // 91136 B  (2 CTAs/SM fit)

// ---------------- device scratch ----------------
__device__ __half g_q16[(size_t)BH * S * D];
__device__ __half g_k16[(size_t)BH * S * D];
__device__ __half g_v16[(size_t)BH * S * D];
// p16 fragments: [cta][kt][warp][kb(8)][lane(32)] x uint4 (fragment-native layout)
__device__ uint4  g_p[(size_t)NCTA * NTILES * NW * 8 * 32];

// ---------------- helpers ----------------
__device__ __forceinline__ uint32_t su32(const void* p) {
    uint32_t a;
    asm("{ .reg .u64 t; cvta.to.shared.u64 t, %1; cvt.u32.u64 %0, t; }" : "=r"(a) : "l"(p));
    return a;
}
__device__ __forceinline__ void cpa16(uint32_t d, const void* s) {
    asm volatile("cp.async.cg.shared.global [%0], [%1], 16;" :: "r"(d), "l"(s));
}
#define CP_COMMIT() asm volatile("cp.async.commit_group;" ::: "memory")
#define CP_WAIT0()  asm volatile("cp.async.wait_group 0;" ::: "memory")

#define LDSM4(r0, r1, r2, r3, a) \
    asm volatile("ldmatrix.sync.aligned.m8n8.x4.shared.b16 {%0,%1,%2,%3}, [%4];" \
                 : "=r"(r0), "=r"(r1), "=r"(r2), "=r"(r3) : "r"(a))
#define LDSM4T(r0, r1, r2, r3, a) \
    asm volatile("ldmatrix.sync.aligned.m8n8.x4.trans.shared.b16 {%0,%1,%2,%3}, [%4];" \
                 : "=r"(r0), "=r"(r1), "=r"(r2), "=r"(r3) : "r"(a))

__device__ __forceinline__ void mma_f16(float4& c, uint32_t a0, uint32_t a1,
                                        uint32_t a2, uint32_t a3,
                                        uint32_t b0, uint32_t b1) {
    asm volatile(
        "mma.sync.aligned.m16n8k16.row.col.f32.f16.f16.f32 "
        "{%0,%1,%2,%3}, {%4,%5,%6,%7}, {%8,%9}, {%0,%1,%2,%3};"
        : "+f"(c.x), "+f"(c.y), "+f"(c.z), "+f"(c.w)
        : "r"(a0), "r"(a1), "r"(a2), "r"(a3), "r"(b0), "r"(b1));
}
__device__ __forceinline__ uint32_t packh2(float a, float b) {
    __half2 h = __floats2half2_rn(a, b);
    return *(uint32_t*)&h;
}
__device__ __forceinline__ float2 unpackh2(uint32_t u) {
    return __half22float2(*(__half2*)&u);
}

// 128-row fp16 tile -> padded smem (8 chunks/thread)
__device__ __forceinline__ void load_tile128(uint32_t sdst, const __half* g, int tid) {
#pragma unroll
    for (int it = 0; it < 8; it++) {
        int f = tid + it * THREADS;
        int r = f >> 3, c = f & 7;
        cpa16(sdst + r * RSB + c * 16, g + r * 64 + c * 8);
    }
}
// 64-row Q tile
__device__ __forceinline__ void load_tile64(uint32_t sdst, const __half* g, int tid) {
#pragma unroll
    for (int it = 0; it < 4; it++) {
        int f = tid + it * THREADS;
        int r = f >> 3, c = f & 7;
        cpa16(sdst + r * RSB + c * 16, g + r * 64 + c * 8);
    }
}

// ---------------- prep: fp32 -> fp16 (Q scaled by 1/T) ----------------
__global__ void prep16(const float* __restrict__ q, const float* __restrict__ k,
                       const float* __restrict__ v) {
    const int N4 = BH * S * D / 4;
    int i = blockIdx.x * blockDim.x + threadIdx.x;
    if (i >= N4) return;
    float4 a = ((const float4*)q)[i];
    float4 b = ((const float4*)k)[i];
    float4 c = ((const float4*)v)[i];
    __half2* q2 = (__half2*)g_q16;
    __half2* k2 = (__half2*)g_k16;
    __half2* v2 = (__half2*)g_v16;
    q2[2 * i]     = __floats2half2_rn(a.x * INV_T, a.y * INV_T);
    q2[2 * i + 1] = __floats2half2_rn(a.z * INV_T, a.w * INV_T);
    k2[2 * i]     = __floats2half2_rn(b.x, b.y);
    k2[2 * i + 1] = __floats2half2_rn(b.z, b.w);
    v2[2 * i]     = __floats2half2_rn(c.x, c.y);
    v2[2 * i + 1] = __floats2half2_rn(c.z, c.w);
}

// ---------------- main fused attention ----------------
__global__ __launch_bounds__(THREADS, 2)
void attn_main(const int* __restrict__ mask,
               float* __restrict__ out, float* __restrict__ attn)
{
    extern __shared__ char smem[];
    const uint32_t sb = su32(smem);
    const int tid = threadIdx.x;
    const int w   = tid >> 5;
    const int L   = tid & 31;
    const int bh  = blockIdx.y;
    const int q0  = blockIdx.x * QT;
    const int cta = bh * gridDim.x + blockIdx.x;

    const __half* qg = g_q16 + ((size_t)bh * S + q0) * D;
    const __half* kg = g_k16 + (size_t)bh * S * D;
    const __half* vg = g_v16 + (size_t)bh * S * D;

    const uint32_t sQ = sb + SM_Q;
    const uint32_t sK[2] = { sb + SM_K0, sb + SM_K1 };
    const uint32_t sV[2] = { sb + SM_V0, sb + SM_V1 };
    float* mf = (float*)(smem + SM_MASK);

    // prologue: Q + K0
    load_tile64(sQ, qg, tid);
    load_tile128(sK[0], kg, tid);
    CP_COMMIT();
    {
        const int* mp = mask + (size_t)(bh >> 4) * S;
        for (int i = tid; i < S; i += THREADS) mf[i] = mp[i] ? 1.0f : 0.0f;
    }
    CP_WAIT0();
    __syncthreads();

    const uint32_t q_part  = ((L & 7) + ((L >> 3) & 1) * 8) * RSB + (L >> 4) * 16;
    const uint32_t qbase   = sQ + w * 16 * RSB + q_part;
    const uint32_t ka_part = (L & 7) * RSB + (L >> 3) * 16;
    const uint32_t va_part = L * RSB;
    const int      c_base  = 2 * (L & 3);

    uint32_t qa[4][4];
#pragma unroll
    for (int ks = 0; ks < 4; ks++)
        LDSM4(qa[ks][0], qa[ks][1], qa[ks][2], qa[ks][3], qbase + ks * 32);

    float sum_lo = 0.0f, sum_hi = 0.0f;

    // ================= pass 1: QK^T, exp, store p16 fragments, row sums =====
    for (int kt = 0; kt < NTILES; kt++) {
        const int cur = kt & 1;
        if (kt + 1 < NTILES) {
            load_tile128(sK[cur ^ 1], kg + (size_t)(kt + 1) * NT * D, tid);
            CP_COMMIT();
        }
        uint4* pbase = g_p + (((size_t)cta * NTILES + kt) * NW + w) * (8 * 32) + L;
        const float* mrow = mf + kt * NT;

        uint4 pk;
#pragma unroll
        for (int nb = 0; nb < 16; nb++) {
            uint32_t kaddr = sK[cur] + nb * 8 * RSB + ka_part;
            uint32_t b0, b1, b2, b3, b4, b5, b6, b7;
            LDSM4(b0, b1, b2, b3, kaddr);
            LDSM4(b4, b5, b6, b7, kaddr + 64);
            float4 cf = make_float4(0.f, 0.f, 0.f, 0.f);
            mma_f16(cf, qa[0][0], qa[0][1], qa[0][2], qa[0][3], b0, b1);
            mma_f16(cf, qa[1][0], qa[1][1], qa[1][2], qa[1][3], b2, b3);
            mma_f16(cf, qa[2][0], qa[2][1], qa[2][2], qa[2][3], b4, b5);
            mma_f16(cf, qa[3][0], qa[3][1], qa[3][2], qa[3][3], b6, b7);

            int c0 = nb * 8 + c_base;
            float m0 = mrow[c0], m1 = mrow[c0 + 1];
            float e0 = __expf(cf.x) * m0;
            float e1 = __expf(cf.y) * m1;
            float e2 = __expf(cf.z) * m0;
            float e3 = __expf(cf.w) * m1;
            sum_lo += e0 + e1;
            sum_hi += e2 + e3;
            if ((nb & 1) == 0) {
                pk.x = packh2(e0, e1);          // rlo, k-cols 0..7 of kb
                pk.y = packh2(e2, e3);          // rhi
            } else {
                pk.z = packh2(e0, e1);          // rlo, k-cols 8..15
                pk.w = packh2(e2, e3);          // rhi
                pbase[(nb >> 1) * 32] = pk;     // lanes contiguous -> 512B/warp store
            }
        }
        if (kt + 1 < NTILES) CP_WAIT0();
        __syncthreads();
    }

    // quad reduction -> full row sums
#pragma unroll
    for (int m = 1; m < 4; m <<= 1) {
        sum_lo += __shfl_xor_sync(0xffffffffu, sum_lo, m);
        sum_hi += __shfl_xor_sync(0xffffffffu, sum_hi, m);
    }
    const float inv_lo = 1.0f / sum_lo;
    const float inv_hi = 1.0f / sum_hi;

    // ================= pass 2: attn write + PV (no QK, no exp) =============
    load_tile128(sV[0], vg, tid);
    CP_COMMIT();
    CP_WAIT0();
    __syncthreads();

    float4 oc[8];
#pragma unroll
    for (int nb = 0; nb < 8; nb++) oc[nb] = make_float4(0.f, 0.f, 0.f, 0.f);

    float* alo = attn + ((size_t)bh * S + q0 + w * 16 + (L >> 2)) * S;
    float* ahi = alo + 8 * (size_t)S;

    for (int kt = 0; kt < NTILES; kt++) {
        const int cur = kt & 1;
        if (kt + 1 < NTILES) {
            load_tile128(sV[cur ^ 1], vg + (size_t)(kt + 1) * NT * D, tid);
            CP_COMMIT();
        }
        const uint4* pbase = g_p + (((size_t)cta * NTILES + kt) * NW + w) * (8 * 32) + L;
        uint4 pa[8];
#pragma unroll
        for (int kb = 0; kb < 8; kb++) pa[kb] = pbase[kb * 32];   // MLP=8 LDG.128

        // attention write: attn = p16 * inv
#pragma unroll
        for (int kb = 0; kb < 8; kb++) {
            int c0 = kt * NT + 16 * kb + c_base;
            float2 f0 = unpackh2(pa[kb].x);
            float2 f1 = unpackh2(pa[kb].y);
            float2 f2 = unpackh2(pa[kb].z);
            float2 f3 = unpackh2(pa[kb].w);
            *(float2*)(alo + c0)     = make_float2(f0.x * inv_lo, f0.y * inv_lo);
            *(float2*)(ahi + c0)     = make_float2(f1.x * inv_hi, f1.y * inv_hi);
            *(float2*)(alo + c0 + 8) = make_float2(f2.x * inv_lo, f2.y * inv_lo);
            *(float2*)(ahi + c0 + 8) = make_float2(f3.x * inv_hi, f3.y * inv_hi);
        }

        // PV: O_un += P16 (16x128) * V (128x64)
#pragma unroll
        for (int nb = 0; nb < 8; nb++) {
#pragma unroll
            for (int kb2 = 0; kb2 < 4; kb2++) {
                uint32_t vaddr = sV[cur] + kb2 * 32 * RSB + nb * 16 + va_part;
                uint32_t v0, v1, v2, v3;
                LDSM4T(v0, v1, v2, v3, vaddr);
                const uint4& A0 = pa[2 * kb2];
                const uint4& A1 = pa[2 * kb2 + 1];
                mma_f16(oc[nb], A0.x, A0.y, A0.z, A0.w, v0, v1);
                mma_f16(oc[nb], A1.x, A1.y, A1.z, A1.w, v2, v3);
            }
        }

        if (kt + 1 < NTILES) CP_WAIT0();
        __syncthreads();
    }

    // ---- output write: O = O_un * inv ----
    float* olo = out + ((size_t)bh * S + q0 + w * 16 + (L >> 2)) * D + c_base;
    float* ohi = olo + 8 * D;
#pragma unroll
    for (int nb = 0; nb < 8; nb++) {
        *(float2*)(olo + nb * 8) = make_float2(oc[nb].x * inv_lo, oc[nb].y * inv_lo);
        *(float2*)(ohi + nb * 8) = make_float2(oc[nb].z * inv_hi, oc[nb].w * inv_hi);
    }
}

// ---------------- launch ----------------
extern "C" void kernel_launch(void* const* d_in, const int* in_sizes, int n_in,
                              void* d_out, int out_size)
{
    const float* q    = (const float*)d_in[0];
    const float* k    = (const float*)d_in[1];
    const float* v    = (const float*)d_in[2];
    const int*   mask = (const int*)  d_in[3];

    float* out  = (float*)d_out;
    float* attn = out + (size_t)BH * S * D;

    cudaFuncSetAttribute(attn_main, cudaFuncAttributeMaxDynamicSharedMemorySize, SMEM_SZ);

    const int N4 = BH * S * D / 4;
    prep16<<<(N4 + 255) / 256, 256>>>(q, k, v);
    attn_main<<<dim3(S / QT, BH), THREADS, SMEM_SZ>>>(mask, out, attn);
}

// round 5
// speedup vs baseline: 8.1049x; 1.0553x over previous
#include <cuda_runtime.h>
#include <cuda_fp16.h>
#include <stdint.h>

// ---------------- problem constants ----------------
constexpr int B = 2, H = 16, S = 2048, D = 64;
constexpr int BH = B * H;
constexpr float INV_T = 1.0f / 32.0f;

constexpr int QT = 128;           // query rows per CTA
constexpr int NT = 128;           // keys per tile
constexpr int NTILES = S / NT;    // 16
constexpr int THREADS = 256;      // 8 warps, warp w owns q-rows 16w..16w+15

// smem: rows of 64 fp16 padded to 72 (144B) -> conflict-free ldmatrix
constexpr int RSB = 144;
constexpr int TILE_BYTES = 128 * RSB;   // 18432

constexpr int SM_Q    = 0;
constexpr int SM_K0   = SM_Q  + TILE_BYTES;
constexpr int SM_K1   = SM_K0 + TILE_BYTES;
constexpr int SM_V0   = SM_K1 + TILE_BYTES;
constexpr int SM_V1   = SM_V0 + TILE_BYTES;
constexpr int SM_MASK = SM_V1 + TILE_BYTES;
constexpr int SMEM_SZ = SM_MASK + S * 4;      // 100352 B -> 2 CTAs/SM

// ---------------- device fp16 copies ----------------
__device__ __half g_q16[(size_t)BH * S * D];
__device__ __half g_k16[(size_t)BH * S * D];
__device__ __half g_v16[(size_t)BH * S * D];

// ---------------- helpers ----------------
__device__ __forceinline__ uint32_t su32(const void* p) {
    uint32_t a;
    asm("{ .reg .u64 t; cvta.to.shared.u64 t, %1; cvt.u32.u64 %0, t; }" : "=r"(a) : "l"(p));
    return a;
}
__device__ __forceinline__ void cpa16(uint32_t d, const void* s) {
    asm volatile("cp.async.cg.shared.global [%0], [%1], 16;" :: "r"(d), "l"(s));
}
#define CP_COMMIT() asm volatile("cp.async.commit_group;" ::: "memory")
#define CP_WAIT0()  asm volatile("cp.async.wait_group 0;" ::: "memory")

#define LDSM4(r0, r1, r2, r3, a) \
    asm volatile("ldmatrix.sync.aligned.m8n8.x4.shared.b16 {%0,%1,%2,%3}, [%4];" \
                 : "=r"(r0), "=r"(r1), "=r"(r2), "=r"(r3) : "r"(a))
#define LDSM4T(r0, r1, r2, r3, a) \
    asm volatile("ldmatrix.sync.aligned.m8n8.x4.trans.shared.b16 {%0,%1,%2,%3}, [%4];" \
                 : "=r"(r0), "=r"(r1), "=r"(r2), "=r"(r3) : "r"(a))

__device__ __forceinline__ void mma_f16(float4& c, uint32_t a0, uint32_t a1,
                                        uint32_t a2, uint32_t a3,
                                        uint32_t b0, uint32_t b1) {
    asm volatile(
        "mma.sync.aligned.m16n8k16.row.col.f32.f16.f16.f32 "
        "{%0,%1,%2,%3}, {%4,%5,%6,%7}, {%8,%9}, {%0,%1,%2,%3};"
        : "+f"(c.x), "+f"(c.y), "+f"(c.z), "+f"(c.w)
        : "r"(a0), "r"(a1), "r"(a2), "r"(a3), "r"(b0), "r"(b1));
}
__device__ __forceinline__ uint32_t packh2(float a, float b) {
    __half2 h = __floats2half2_rn(a, b);
    return *(uint32_t*)&h;
}

__device__ __forceinline__ void load_tile(uint32_t sdst, const __half* g, int tid) {
#pragma unroll
    for (int it = 0; it < 4; it++) {
        int f = tid + it * THREADS;
        int r = f >> 3, c = f & 7;
        cpa16(sdst + r * RSB + c * 16, g + r * 64 + c * 8);
    }
}

// ---------------- prep: fp32 -> fp16 (Q scaled by 1/T) ----------------
__global__ void prep16(const float* __restrict__ q, const float* __restrict__ k,
                       const float* __restrict__ v) {
    const int N4 = BH * S * D / 4;
    int i = blockIdx.x * blockDim.x + threadIdx.x;
    if (i >= N4) return;
    float4 a = ((const float4*)q)[i];
    float4 b = ((const float4*)k)[i];
    float4 c = ((const float4*)v)[i];
    __half2* q2 = (__half2*)g_q16;
    __half2* k2 = (__half2*)g_k16;
    __half2* v2 = (__half2*)g_v16;
    q2[2 * i]     = __floats2half2_rn(a.x * INV_T, a.y * INV_T);
    q2[2 * i + 1] = __floats2half2_rn(a.z * INV_T, a.w * INV_T);
    k2[2 * i]     = __floats2half2_rn(b.x, b.y);
    k2[2 * i + 1] = __floats2half2_rn(b.z, b.w);
    v2[2 * i]     = __floats2half2_rn(c.x, c.y);
    v2[2 * i + 1] = __floats2half2_rn(c.z, c.w);
}

// ---------------- main fused attention ----------------
__global__ __launch_bounds__(THREADS, 2)
void attn_main(const int* __restrict__ mask,
               float* __restrict__ out, float* __restrict__ attn)
{
    extern __shared__ char smem[];
    const uint32_t sb = su32(smem);
    const int tid = threadIdx.x;
    const int w   = tid >> 5;
    const int L   = tid & 31;
    const int bh  = blockIdx.y;
    const int q0  = blockIdx.x * QT;

    const __half* qg = g_q16 + ((size_t)bh * S + q0) * D;
    const __half* kg = g_k16 + (size_t)bh * S * D;
    const __half* vg = g_v16 + (size_t)bh * S * D;

    const uint32_t sQ = sb + SM_Q;
    const uint32_t sK[2] = { sb + SM_K0, sb + SM_K1 };
    const uint32_t sV[2] = { sb + SM_V0, sb + SM_V1 };
    float* mf = (float*)(smem + SM_MASK);

    load_tile(sQ, qg, tid);
    load_tile(sK[0], kg, tid);
    CP_COMMIT();
    {
        const int* mp = mask + (size_t)(bh >> 4) * S;
        for (int i = tid; i < S; i += THREADS) mf[i] = mp[i] ? 1.0f : 0.0f;
    }
    CP_WAIT0();
    __syncthreads();

    const uint32_t q_part  = ((L & 7) + ((L >> 3) & 1) * 8) * RSB + (L >> 4) * 16;
    const uint32_t qbase   = sQ + w * 16 * RSB + q_part;
    const uint32_t ka_part = (L & 7) * RSB + (L >> 3) * 16;
    const uint32_t va_part = L * RSB;
    const int      c_base  = 2 * (L & 3);

    uint32_t qa[4][4];
#pragma unroll
    for (int ks = 0; ks < 4; ks++)
        LDSM4(qa[ks][0], qa[ks][1], qa[ks][2], qa[ks][3], qbase + ks * 32);

    float sum_lo = 0.0f, sum_hi = 0.0f;

    // ================= pass 1: row sums (one cf live at a time) =============
    for (int kt = 0; kt < NTILES; kt++) {
        const int cur = kt & 1;
        if (kt + 1 < NTILES) {
            load_tile(sK[cur ^ 1], kg + (size_t)(kt + 1) * NT * D, tid);
            CP_COMMIT();
        }
        const float* mrow = mf + kt * NT;
#pragma unroll
        for (int nb = 0; nb < 16; nb++) {
            uint32_t kaddr = sK[cur] + nb * 8 * RSB + ka_part;
            uint32_t b0, b1, b2, b3, b4, b5, b6, b7;
            LDSM4(b0, b1, b2, b3, kaddr);
            LDSM4(b4, b5, b6, b7, kaddr + 64);
            float4 cf = make_float4(0.f, 0.f, 0.f, 0.f);
            mma_f16(cf, qa[0][0], qa[0][1], qa[0][2], qa[0][3], b0, b1);
            mma_f16(cf, qa[1][0], qa[1][1], qa[1][2], qa[1][3], b2, b3);
            mma_f16(cf, qa[2][0], qa[2][1], qa[2][2], qa[2][3], b4, b5);
            mma_f16(cf, qa[3][0], qa[3][1], qa[3][2], qa[3][3], b6, b7);
            int c0 = nb * 8 + c_base;
            float m0 = mrow[c0], m1 = mrow[c0 + 1];
            sum_lo += m0 * __expf(cf.x) + m1 * __expf(cf.y);
            sum_hi += m0 * __expf(cf.z) + m1 * __expf(cf.w);
        }
        if (kt + 1 < NTILES) CP_WAIT0();
        __syncthreads();
    }

#pragma unroll
    for (int m = 1; m < 4; m <<= 1) {
        sum_lo += __shfl_xor_sync(0xffffffffu, sum_lo, m);
        sum_hi += __shfl_xor_sync(0xffffffffu, sum_hi, m);
    }
    const float inv_lo = 1.0f / sum_lo;
    const float inv_hi = 1.0f / sum_hi;

    // ================= pass 2: recompute QK, attn write, PV =================
    load_tile(sK[0], kg, tid);
    load_tile(sV[0], vg, tid);
    CP_COMMIT();
    CP_WAIT0();
    __syncthreads();

    float4 oc[8];
#pragma unroll
    for (int nb = 0; nb < 8; nb++) oc[nb] = make_float4(0.f, 0.f, 0.f, 0.f);

    float* alo = attn + ((size_t)bh * S + q0 + w * 16 + (L >> 2)) * S;
    float* ahi = alo + 8 * (size_t)S;

    for (int kt = 0; kt < NTILES; kt++) {
        const int cur = kt & 1;
        if (kt + 1 < NTILES) {
            load_tile(sK[cur ^ 1], kg + (size_t)(kt + 1) * NT * D, tid);
            load_tile(sV[cur ^ 1], vg + (size_t)(kt + 1) * NT * D, tid);
            CP_COMMIT();
        }
        const float* mrow = mf + kt * NT;

        // process 32 keys (one kb2 group) at a time to keep registers low
#pragma unroll
        for (int kb2 = 0; kb2 < 4; kb2++) {
            float4 cf[4];
            uint32_t a16[2][4];
#pragma unroll
            for (int i = 0; i < 4; i++) {
                int nb = kb2 * 4 + i;
                uint32_t kaddr = sK[cur] + nb * 8 * RSB + ka_part;
                uint32_t b0, b1, b2, b3, b4, b5, b6, b7;
                LDSM4(b0, b1, b2, b3, kaddr);
                LDSM4(b4, b5, b6, b7, kaddr + 64);
                cf[i] = make_float4(0.f, 0.f, 0.f, 0.f);
                mma_f16(cf[i], qa[0][0], qa[0][1], qa[0][2], qa[0][3], b0, b1);
                mma_f16(cf[i], qa[1][0], qa[1][1], qa[1][2], qa[1][3], b2, b3);
                mma_f16(cf[i], qa[2][0], qa[2][1], qa[2][2], qa[2][3], b4, b5);
                mma_f16(cf[i], qa[3][0], qa[3][1], qa[3][2], qa[3][3], b6, b7);
            }
#pragma unroll
            for (int i = 0; i < 4; i++) {
                int nb = kb2 * 4 + i;
                int c0 = nb * 8 + c_base;
                float m0 = mrow[c0], m1 = mrow[c0 + 1];
                float e0 = __expf(cf[i].x) * m0;
                float e1 = __expf(cf[i].y) * m1;
                float e2 = __expf(cf[i].z) * m0;
                float e3 = __expf(cf[i].w) * m1;
                *(float2*)(alo + kt * NT + c0) = make_float2(e0 * inv_lo, e1 * inv_lo);
                *(float2*)(ahi + kt * NT + c0) = make_float2(e2 * inv_hi, e3 * inv_hi);
                a16[i >> 1][(i & 1) * 2]     = packh2(e0, e1);
                a16[i >> 1][(i & 1) * 2 + 1] = packh2(e2, e3);
            }
            // partial PV for these 32 keys
#pragma unroll
            for (int nbo = 0; nbo < 8; nbo++) {
                uint32_t vaddr = sV[cur] + kb2 * 32 * RSB + nbo * 16 + va_part;
                uint32_t v0, v1, v2, v3;
                LDSM4T(v0, v1, v2, v3, vaddr);
                mma_f16(oc[nbo], a16[0][0], a16[0][1], a16[0][2], a16[0][3], v0, v1);
                mma_f16(oc[nbo], a16[1][0], a16[1][1], a16[1][2], a16[1][3], v2, v3);
            }
        }

        if (kt + 1 < NTILES) CP_WAIT0();
        __syncthreads();
    }

    // ---- output write: O = O_un * inv ----
    float* olo = out + ((size_t)bh * S + q0 + w * 16 + (L >> 2)) * D + c_base;
    float* ohi = olo + 8 * D;
#pragma unroll
    for (int nb = 0; nb < 8; nb++) {
        *(float2*)(olo + nb * 8) = make_float2(oc[nb].x * inv_lo, oc[nb].y * inv_lo);
        *(float2*)(ohi + nb * 8) = make_float2(oc[nb].z * inv_hi, oc[nb].w * inv_hi);
    }
}

// ---------------- launch ----------------
extern "C" void kernel_launch(void* const* d_in, const int* in_sizes, int n_in,
                              void* d_out, int out_size)
{
    const float* q    = (const float*)d_in[0];
    const float* k    = (const float*)d_in[1];
    const float* v    = (const float*)d_in[2];
    const int*   mask = (const int*)  d_in[3];

    float* out  = (float*)d_out;
    float* attn = out + (size_t)BH * S * D;

    cudaFuncSetAttribute(attn_main, cudaFuncAttributeMaxDynamicSharedMemorySize, SMEM_SZ);

    const int N4 = BH * S * D / 4;
    prep16<<<(N4 + 255) / 256, 256>>>(q, k, v);
    attn_main<<<dim3(S / QT, BH), THREADS, SMEM_SZ>>>(mask, out, attn);
}

// round 6
// speedup vs baseline: 8.6766x; 1.0705x over previous
#include <cuda_runtime.h>
#include <cuda_fp16.h>
#include <stdint.h>

// ---------------- problem constants ----------------
constexpr int B = 2, H = 16, S = 2048, D = 64;
constexpr int BH = B * H;
constexpr float INV_T = 1.0f / 32.0f;

constexpr int QT = 128;           // query rows per CTA
constexpr int NT = 128;           // keys per tile
constexpr int NTILES = S / NT;    // 16
constexpr int THREADS = 256;      // 8 warps, warp w owns q-rows 16w..16w+15

// smem: rows of 64 fp16 padded to 72 (144B) -> conflict-free ldmatrix
constexpr int RSB = 144;
constexpr int TILE_BYTES = 128 * RSB;   // 18432

constexpr int SM_Q    = 0;
constexpr int SM_K0   = SM_Q  + TILE_BYTES;
constexpr int SM_K1   = SM_K0 + TILE_BYTES;
constexpr int SM_V0   = SM_K1 + TILE_BYTES;
constexpr int SM_V1   = SM_V0 + TILE_BYTES;
constexpr int SM_MASK = SM_V1 + TILE_BYTES;
constexpr int SMEM_SZ = SM_MASK + S * 4;      // 100352 B -> 2 CTAs/SM

// ---------------- device fp16 copies ----------------
__device__ __half g_q16[(size_t)BH * S * D];
__device__ __half g_k16[(size_t)BH * S * D];
__device__ __half g_v16[(size_t)BH * S * D];

// ---------------- helpers ----------------
__device__ __forceinline__ uint32_t su32(const void* p) {
    uint32_t a;
    asm("{ .reg .u64 t; cvta.to.shared.u64 t, %1; cvt.u32.u64 %0, t; }" : "=r"(a) : "l"(p));
    return a;
}
__device__ __forceinline__ void cpa16(uint32_t d, const void* s) {
    asm volatile("cp.async.cg.shared.global [%0], [%1], 16;" :: "r"(d), "l"(s));
}
#define CP_COMMIT() asm volatile("cp.async.commit_group;" ::: "memory")
#define CP_WAIT0()  asm volatile("cp.async.wait_group 0;" ::: "memory")

#define LDSM4(r0, r1, r2, r3, a) \
    asm volatile("ldmatrix.sync.aligned.m8n8.x4.shared.b16 {%0,%1,%2,%3}, [%4];" \
                 : "=r"(r0), "=r"(r1), "=r"(r2), "=r"(r3) : "r"(a))
#define LDSM4T(r0, r1, r2, r3, a) \
    asm volatile("ldmatrix.sync.aligned.m8n8.x4.trans.shared.b16 {%0,%1,%2,%3}, [%4];" \
                 : "=r"(r0), "=r"(r1), "=r"(r2), "=r"(r3) : "r"(a))

__device__ __forceinline__ void mma_f16(float4& c, uint32_t a0, uint32_t a1,
                                        uint32_t a2, uint32_t a3,
                                        uint32_t b0, uint32_t b1) {
    asm volatile(
        "mma.sync.aligned.m16n8k16.row.col.f32.f16.f16.f32 "
        "{%0,%1,%2,%3}, {%4,%5,%6,%7}, {%8,%9}, {%0,%1,%2,%3};"
        : "+f"(c.x), "+f"(c.y), "+f"(c.z), "+f"(c.w)
        : "r"(a0), "r"(a1), "r"(a2), "r"(a3), "r"(b0), "r"(b1));
}
__device__ __forceinline__ uint32_t packh2(float a, float b) {
    __half2 h = __floats2half2_rn(a, b);
    return *(uint32_t*)&h;
}
__device__ __forceinline__ float2 shfl_xor_f2(float2 v, int m) {
    v.x = __shfl_xor_sync(0xffffffffu, v.x, m);
    v.y = __shfl_xor_sync(0xffffffffu, v.y, m);
    return v;
}
// 4x4 transpose of float2 a[4] across a quad of lanes (q = lane&3).
// After: lane q's a[i] = original lane i's a[q].
__device__ __forceinline__ void quad_transpose_f2(float2 a[4], int q) {
    {
        float2 v = (q & 1) ? a[0] : a[1];
        v = shfl_xor_f2(v, 1);
        if (q & 1) a[0] = v; else a[1] = v;
        float2 u = (q & 1) ? a[2] : a[3];
        u = shfl_xor_f2(u, 1);
        if (q & 1) a[2] = u; else a[3] = u;
    }
    {
        float2 v = (q & 2) ? a[0] : a[2];
        v = shfl_xor_f2(v, 2);
        if (q & 2) a[0] = v; else a[2] = v;
        float2 u = (q & 2) ? a[1] : a[3];
        u = shfl_xor_f2(u, 2);
        if (q & 2) a[1] = u; else a[3] = u;
    }
}

__device__ __forceinline__ void load_tile(uint32_t sdst, const __half* g, int tid) {
#pragma unroll
    for (int it = 0; it < 4; it++) {
        int f = tid + it * THREADS;
        int r = f >> 3, c = f & 7;
        cpa16(sdst + r * RSB + c * 16, g + r * 64 + c * 8);
    }
}

// ---------------- prep: fp32 -> fp16 (Q scaled by 1/T) ----------------
__global__ void prep16(const float* __restrict__ q, const float* __restrict__ k,
                       const float* __restrict__ v) {
    const int N4 = BH * S * D / 4;
    int i = blockIdx.x * blockDim.x + threadIdx.x;
    if (i >= N4) return;
    float4 a = ((const float4*)q)[i];
    float4 b = ((const float4*)k)[i];
    float4 c = ((const float4*)v)[i];
    __half2* q2 = (__half2*)g_q16;
    __half2* k2 = (__half2*)g_k16;
    __half2* v2 = (__half2*)g_v16;
    q2[2 * i]     = __floats2half2_rn(a.x * INV_T, a.y * INV_T);
    q2[2 * i + 1] = __floats2half2_rn(a.z * INV_T, a.w * INV_T);
    k2[2 * i]     = __floats2half2_rn(b.x, b.y);
    k2[2 * i + 1] = __floats2half2_rn(b.z, b.w);
    v2[2 * i]     = __floats2half2_rn(c.x, c.y);
    v2[2 * i + 1] = __floats2half2_rn(c.z, c.w);
}

// ---------------- main fused attention ----------------
__global__ __launch_bounds__(THREADS, 2)
void attn_main(const int* __restrict__ mask,
               float* __restrict__ out, float* __restrict__ attn)
{
    extern __shared__ char smem[];
    const uint32_t sb = su32(smem);
    const int tid = threadIdx.x;
    const int w   = tid >> 5;
    const int L   = tid & 31;
    const int q_  = L & 3;
    const int bh  = blockIdx.y;
    const int q0  = blockIdx.x * QT;

    const __half* qg = g_q16 + ((size_t)bh * S + q0) * D;
    const __half* kg = g_k16 + (size_t)bh * S * D;
    const __half* vg = g_v16 + (size_t)bh * S * D;

    const uint32_t sQ = sb + SM_Q;
    const uint32_t sK[2] = { sb + SM_K0, sb + SM_K1 };
    const uint32_t sV[2] = { sb + SM_V0, sb + SM_V1 };
    float* mf = (float*)(smem + SM_MASK);

    load_tile(sQ, qg, tid);
    load_tile(sK[0], kg, tid);
    CP_COMMIT();
    {
        const int* mp = mask + (size_t)(bh >> 4) * S;
        for (int i = tid; i < S; i += THREADS) mf[i] = mp[i] ? 1.0f : 0.0f;
    }
    CP_WAIT0();
    __syncthreads();

    const uint32_t q_part  = ((L & 7) + ((L >> 3) & 1) * 8) * RSB + (L >> 4) * 16;
    const uint32_t qbase   = sQ + w * 16 * RSB + q_part;
    const uint32_t ka_part = (L & 7) * RSB + (L >> 3) * 16;
    const uint32_t va_part = L * RSB;
    const int      c_base  = 2 * q_;

    uint32_t qa[4][4];
#pragma unroll
    for (int ks = 0; ks < 4; ks++)
        LDSM4(qa[ks][0], qa[ks][1], qa[ks][2], qa[ks][3], qbase + ks * 32);

    float sum_lo = 0.0f, sum_hi = 0.0f;

    // ================= pass 1: row sums =============
    for (int kt = 0; kt < NTILES; kt++) {
        const int cur = kt & 1;
        if (kt + 1 < NTILES) {
            load_tile(sK[cur ^ 1], kg + (size_t)(kt + 1) * NT * D, tid);
            CP_COMMIT();
        }
        const float* mrow = mf + kt * NT;
#pragma unroll
        for (int nb = 0; nb < 16; nb++) {
            uint32_t kaddr = sK[cur] + nb * 8 * RSB + ka_part;
            uint32_t b0, b1, b2, b3, b4, b5, b6, b7;
            LDSM4(b0, b1, b2, b3, kaddr);
            LDSM4(b4, b5, b6, b7, kaddr + 64);
            float4 cf = make_float4(0.f, 0.f, 0.f, 0.f);
            mma_f16(cf, qa[0][0], qa[0][1], qa[0][2], qa[0][3], b0, b1);
            mma_f16(cf, qa[1][0], qa[1][1], qa[1][2], qa[1][3], b2, b3);
            mma_f16(cf, qa[2][0], qa[2][1], qa[2][2], qa[2][3], b4, b5);
            mma_f16(cf, qa[3][0], qa[3][1], qa[3][2], qa[3][3], b6, b7);
            int c0 = nb * 8 + c_base;
            float m0 = mrow[c0], m1 = mrow[c0 + 1];
            sum_lo += m0 * __expf(cf.x) + m1 * __expf(cf.y);
            sum_hi += m0 * __expf(cf.z) + m1 * __expf(cf.w);
        }
        if (kt + 1 < NTILES) CP_WAIT0();
        __syncthreads();
    }

#pragma unroll
    for (int m = 1; m < 4; m <<= 1) {
        sum_lo += __shfl_xor_sync(0xffffffffu, sum_lo, m);
        sum_hi += __shfl_xor_sync(0xffffffffu, sum_hi, m);
    }
    const float inv_lo = 1.0f / sum_lo;
    const float inv_hi = 1.0f / sum_hi;

    // ================= pass 2: recompute QK, attn write, PV =================
    load_tile(sK[0], kg, tid);
    load_tile(sV[0], vg, tid);
    CP_COMMIT();
    CP_WAIT0();
    __syncthreads();

    float4 oc[8];
#pragma unroll
    for (int nb = 0; nb < 8; nb++) oc[nb] = make_float4(0.f, 0.f, 0.f, 0.f);

    float* arow_lo = attn + ((size_t)bh * S + q0 + w * 16 + (L >> 2)) * S;
    float* arow_hi = arow_lo + 8 * (size_t)S;

    for (int kt = 0; kt < NTILES; kt++) {
        const int cur = kt & 1;
        if (kt + 1 < NTILES) {
            load_tile(sK[cur ^ 1], kg + (size_t)(kt + 1) * NT * D, tid);
            load_tile(sV[cur ^ 1], vg + (size_t)(kt + 1) * NT * D, tid);
            CP_COMMIT();
        }
        const float* mrow = mf + kt * NT;

#pragma unroll
        for (int kb2 = 0; kb2 < 4; kb2++) {
            float4 cf[4];
            uint32_t a16[2][4];
            float2 flo[4], fhi[4];
#pragma unroll
            for (int i = 0; i < 4; i++) {
                int nb = kb2 * 4 + i;
                uint32_t kaddr = sK[cur] + nb * 8 * RSB + ka_part;
                uint32_t b0, b1, b2, b3, b4, b5, b6, b7;
                LDSM4(b0, b1, b2, b3, kaddr);
                LDSM4(b4, b5, b6, b7, kaddr + 64);
                cf[i] = make_float4(0.f, 0.f, 0.f, 0.f);
                mma_f16(cf[i], qa[0][0], qa[0][1], qa[0][2], qa[0][3], b0, b1);
                mma_f16(cf[i], qa[1][0], qa[1][1], qa[1][2], qa[1][3], b2, b3);
                mma_f16(cf[i], qa[2][0], qa[2][1], qa[2][2], qa[2][3], b4, b5);
                mma_f16(cf[i], qa[3][0], qa[3][1], qa[3][2], qa[3][3], b6, b7);
            }
#pragma unroll
            for (int i = 0; i < 4; i++) {
                int nb = kb2 * 4 + i;
                int c0 = nb * 8 + c_base;
                float m0 = mrow[c0], m1 = mrow[c0 + 1];
                float e0 = __expf(cf[i].x) * m0;
                float e1 = __expf(cf[i].y) * m1;
                float e2 = __expf(cf[i].z) * m0;
                float e3 = __expf(cf[i].w) * m1;
                flo[i] = make_float2(e0 * inv_lo, e1 * inv_lo);
                fhi[i] = make_float2(e2 * inv_hi, e3 * inv_hi);
                a16[i >> 1][(i & 1) * 2]     = packh2(e0, e1);
                a16[i >> 1][(i & 1) * 2 + 1] = packh2(e2, e3);
            }
            quad_transpose_f2(flo, q_);
            quad_transpose_f2(fhi, q_);
            {
                int col = kt * NT + kb2 * 32 + 8 * q_;
                __stcs((float4*)(arow_lo + col),
                       make_float4(flo[0].x, flo[0].y, flo[1].x, flo[1].y));
                __stcs((float4*)(arow_lo + col + 4),
                       make_float4(flo[2].x, flo[2].y, flo[3].x, flo[3].y));
                __stcs((float4*)(arow_hi + col),
                       make_float4(fhi[0].x, fhi[0].y, fhi[1].x, fhi[1].y));
                __stcs((float4*)(arow_hi + col + 4),
                       make_float4(fhi[2].x, fhi[2].y, fhi[3].x, fhi[3].y));
            }
#pragma unroll
            for (int nbo = 0; nbo < 8; nbo++) {
                uint32_t vaddr = sV[cur] + kb2 * 32 * RSB + nbo * 16 + va_part;
                uint32_t v0, v1, v2, v3;
                LDSM4T(v0, v1, v2, v3, vaddr);
                mma_f16(oc[nbo], a16[0][0], a16[0][1], a16[0][2], a16[0][3], v0, v1);
                mma_f16(oc[nbo], a16[1][0], a16[1][1], a16[1][2], a16[1][3], v2, v3);
            }
        }

        if (kt + 1 < NTILES) CP_WAIT0();
        __syncthreads();
    }

    // ---- output write: O = O_un * inv ----
    float* olo = out + ((size_t)bh * S + q0 + w * 16 + (L >> 2)) * D + c_base;
    float* ohi = olo + 8 * D;
#pragma unroll
    for (int nb = 0; nb < 8; nb++) {
        *(float2*)(olo + nb * 8) = make_float2(oc[nb].x * inv_lo, oc[nb].y * inv_lo);
        *(float2*)(ohi + nb * 8) = make_float2(oc[nb].z * inv_hi, oc[nb].w * inv_hi);
    }
}

// ---------------- launch ----------------
extern "C" void kernel_launch(void* const* d_in, const int* in_sizes, int n_in,
                              void* d_out, int out_size)
{
    const float* q    = (const float*)d_in[0];
    const float* k    = (const float*)d_in[1];
    const float* v    = (const float*)d_in[2];
    const int*   mask = (const int*)  d_in[3];

    float* out  = (float*)d_out;
    float* attn = out + (size_t)BH * S * D;

    cudaFuncSetAttribute(attn_main, cudaFuncAttributeMaxDynamicSharedMemorySize, SMEM_SZ);

    const int N4 = BH * S * D / 4;
    prep16<<<(N4 + 255) / 256, 256>>>(q, k, v);
    attn_main<<<dim3(S / QT, BH), THREADS, SMEM_SZ>>>(mask, out, attn);
}

// round 7
// speedup vs baseline: 8.8122x; 1.0156x over previous
#include <cuda_runtime.h>
#include <cuda_fp16.h>
#include <stdint.h>

// ---------------- problem constants ----------------
constexpr int B = 2, H = 16, S = 2048, D = 64;
constexpr int BH = B * H;
constexpr float INV_T = 1.0f / 32.0f;

constexpr int QT = 128;           // query rows per CTA
constexpr int NT = 128;           // keys per tile
constexpr int NTILES = S / NT;    // 16
constexpr int THREADS = 256;      // 8 warps

// smem: rows of 64 fp16 padded to 72 (144B) -> conflict-free ldmatrix
constexpr int RSB = 144;
constexpr int TILE_BYTES = 128 * RSB;   // 18432

constexpr int SM_Q    = 0;                       // 18432 (128 rows)
constexpr int SM_B0   = SM_Q  + TILE_BYTES;
constexpr int SM_B1   = SM_B0 + TILE_BYTES;
constexpr int SM_B2   = SM_B1 + TILE_BYTES;
constexpr int SM_B3   = SM_B2 + TILE_BYTES;
constexpr int SM_MASK = SM_B3 + TILE_BYTES;      // 2048 floats
constexpr int SM_INV  = SM_MASK + S * 4;         // 128 floats
constexpr int SMEM_SZ = SM_INV + 512;            // 100864 B -> 2 CTAs/SM

// ---------------- device fp16 copies ----------------
__device__ __half g_q16[(size_t)BH * S * D];
__device__ __half g_k16[(size_t)BH * S * D];
__device__ __half g_v16[(size_t)BH * S * D];

// ---------------- helpers ----------------
__device__ __forceinline__ uint32_t su32(const void* p) {
    uint32_t a;
    asm("{ .reg .u64 t; cvta.to.shared.u64 t, %1; cvt.u32.u64 %0, t; }" : "=r"(a) : "l"(p));
    return a;
}
__device__ __forceinline__ void cpa16(uint32_t d, const void* s) {
    asm volatile("cp.async.cg.shared.global [%0], [%1], 16;" :: "r"(d), "l"(s));
}
#define CP_COMMIT() asm volatile("cp.async.commit_group;" ::: "memory")
#define CP_WAIT0()  asm volatile("cp.async.wait_group 0;" ::: "memory")
#define BARG(id)    asm volatile("bar.sync %0, 128;" :: "r"(id) : "memory")

#define LDSM4(r0, r1, r2, r3, a) \
    asm volatile("ldmatrix.sync.aligned.m8n8.x4.shared.b16 {%0,%1,%2,%3}, [%4];" \
                 : "=r"(r0), "=r"(r1), "=r"(r2), "=r"(r3) : "r"(a))
#define LDSM4T(r0, r1, r2, r3, a) \
    asm volatile("ldmatrix.sync.aligned.m8n8.x4.trans.shared.b16 {%0,%1,%2,%3}, [%4];" \
                 : "=r"(r0), "=r"(r1), "=r"(r2), "=r"(r3) : "r"(a))

__device__ __forceinline__ void mma_f16(float4& c, uint32_t a0, uint32_t a1,
                                        uint32_t a2, uint32_t a3,
                                        uint32_t b0, uint32_t b1) {
    asm volatile(
        "mma.sync.aligned.m16n8k16.row.col.f32.f16.f16.f32 "
        "{%0,%1,%2,%3}, {%4,%5,%6,%7}, {%8,%9}, {%0,%1,%2,%3};"
        : "+f"(c.x), "+f"(c.y), "+f"(c.z), "+f"(c.w)
        : "r"(a0), "r"(a1), "r"(a2), "r"(a3), "r"(b0), "r"(b1));
}
__device__ __forceinline__ uint32_t packh2(float a, float b) {
    __half2 h = __floats2half2_rn(a, b);
    return *(uint32_t*)&h;
}
__device__ __forceinline__ float2 shfl_xor_f2(float2 v, int m) {
    v.x = __shfl_xor_sync(0xffffffffu, v.x, m);
    v.y = __shfl_xor_sync(0xffffffffu, v.y, m);
    return v;
}
// 4x4 transpose of float2 a[4] across a quad of lanes (q = lane&3).
__device__ __forceinline__ void quad_transpose_f2(float2 a[4], int q) {
    {
        float2 v = (q & 1) ? a[0] : a[1];
        v = shfl_xor_f2(v, 1);
        if (q & 1) a[0] = v; else a[1] = v;
        float2 u = (q & 1) ? a[2] : a[3];
        u = shfl_xor_f2(u, 1);
        if (q & 1) a[2] = u; else a[3] = u;
    }
    {
        float2 v = (q & 2) ? a[0] : a[2];
        v = shfl_xor_f2(v, 2);
        if (q & 2) a[0] = v; else a[2] = v;
        float2 u = (q & 2) ? a[1] : a[3];
        u = shfl_xor_f2(u, 2);
        if (q & 2) a[1] = u; else a[3] = u;
    }
}

// 256-thread tile load
__device__ __forceinline__ void load_tile(uint32_t sdst, const __half* g, int tid) {
#pragma unroll
    for (int it = 0; it < 4; it++) {
        int f = tid + it * THREADS;
        int r = f >> 3, c = f & 7;
        cpa16(sdst + r * RSB + c * 16, g + r * 64 + c * 8);
    }
}
// 128-thread (one group) tile load
__device__ __forceinline__ void load_tile_g(uint32_t sdst, const __half* g, int gtid) {
#pragma unroll
    for (int it = 0; it < 8; it++) {
        int f = gtid + it * 128;
        int r = f >> 3, c = f & 7;
        cpa16(sdst + r * RSB + c * 16, g + r * 64 + c * 8);
    }
}

// ---------------- prep: fp32 -> fp16 (Q scaled by 1/T) ----------------
__global__ void prep16(const float* __restrict__ q, const float* __restrict__ k,
                       const float* __restrict__ v) {
    const int N4 = BH * S * D / 4;
    int i = blockIdx.x * blockDim.x + threadIdx.x;
    if (i >= N4) return;
    float4 a = ((const float4*)q)[i];
    float4 b = ((const float4*)k)[i];
    float4 c = ((const float4*)v)[i];
    __half2* q2 = (__half2*)g_q16;
    __half2* k2 = (__half2*)g_k16;
    __half2* v2 = (__half2*)g_v16;
    q2[2 * i]     = __floats2half2_rn(a.x * INV_T, a.y * INV_T);
    q2[2 * i + 1] = __floats2half2_rn(a.z * INV_T, a.w * INV_T);
    k2[2 * i]     = __floats2half2_rn(b.x, b.y);
    k2[2 * i + 1] = __floats2half2_rn(b.z, b.w);
    v2[2 * i]     = __floats2half2_rn(c.x, c.y);
    v2[2 * i + 1] = __floats2half2_rn(c.z, c.w);
}

// ---------------- main fused attention ----------------
__global__ __launch_bounds__(THREADS, 2)
void attn_main(const int* __restrict__ mask,
               float* __restrict__ out, float* __restrict__ attn)
{
    extern __shared__ char smem[];
    const uint32_t sb = su32(smem);
    const int tid = threadIdx.x;
    const int w   = tid >> 5;
    const int L   = tid & 31;
    const int q_  = L & 3;
    const int bh  = blockIdx.y;
    const int q0  = blockIdx.x * QT;

    const __half* qg = g_q16 + ((size_t)bh * S + q0) * D;
    const __half* kg = g_k16 + (size_t)bh * S * D;
    const __half* vg = g_v16 + (size_t)bh * S * D;

    const uint32_t sQ = sb + SM_Q;
    const uint32_t sK[2] = { sb + SM_B0, sb + SM_B1 };
    const uint32_t sV[2] = { sb + SM_B2, sb + SM_B3 };
    float* mf   = (float*)(smem + SM_MASK);
    float* sInv = (float*)(smem + SM_INV);

    load_tile(sQ, qg, tid);
    load_tile(sK[0], kg, tid);
    load_tile(sV[0], vg, tid);
    CP_COMMIT();
    {
        const int* mp = mask + (size_t)(bh >> 4) * S;
        for (int i = tid; i < S; i += THREADS) mf[i] = mp[i] ? 1.0f : 0.0f;
    }
    CP_WAIT0();
    __syncthreads();

    const uint32_t q_part  = ((L & 7) + ((L >> 3) & 1) * 8) * RSB + (L >> 4) * 16;
    const uint32_t ka_part = (L & 7) * RSB + (L >> 3) * 16;
    const uint32_t va_part = L * RSB;
    const int      c_base  = 2 * q_;

    // ===== pass 1: QK + exp + sums + PV (16-row warps, all tiles) =====
    {
        uint32_t qa[4][4];
        const uint32_t qbase = sQ + w * 16 * RSB + q_part;
#pragma unroll
        for (int ks = 0; ks < 4; ks++)
            LDSM4(qa[ks][0], qa[ks][1], qa[ks][2], qa[ks][3], qbase + ks * 32);

        float4 oc[8];
#pragma unroll
        for (int nb = 0; nb < 8; nb++) oc[nb] = make_float4(0.f, 0.f, 0.f, 0.f);
        float sum_lo = 0.0f, sum_hi = 0.0f;

        for (int kt = 0; kt < NTILES; kt++) {
            const int cur = kt & 1;
            if (kt + 1 < NTILES) {
                load_tile(sK[cur ^ 1], kg + (size_t)(kt + 1) * NT * D, tid);
                load_tile(sV[cur ^ 1], vg + (size_t)(kt + 1) * NT * D, tid);
                CP_COMMIT();
            }
            const float* mrow = mf + kt * NT;

#pragma unroll
            for (int kb2 = 0; kb2 < 4; kb2++) {
                float4 cf[4];
                uint32_t a16[2][4];
#pragma unroll
                for (int i = 0; i < 4; i++) {
                    int nb = kb2 * 4 + i;
                    uint32_t kaddr = sK[cur] + nb * 8 * RSB + ka_part;
                    uint32_t b0, b1, b2, b3, b4, b5, b6, b7;
                    LDSM4(b0, b1, b2, b3, kaddr);
                    LDSM4(b4, b5, b6, b7, kaddr + 64);
                    cf[i] = make_float4(0.f, 0.f, 0.f, 0.f);
                    mma_f16(cf[i], qa[0][0], qa[0][1], qa[0][2], qa[0][3], b0, b1);
                    mma_f16(cf[i], qa[1][0], qa[1][1], qa[1][2], qa[1][3], b2, b3);
                    mma_f16(cf[i], qa[2][0], qa[2][1], qa[2][2], qa[2][3], b4, b5);
                    mma_f16(cf[i], qa[3][0], qa[3][1], qa[3][2], qa[3][3], b6, b7);
                }
#pragma unroll
                for (int i = 0; i < 4; i++) {
                    int nb = kb2 * 4 + i;
                    int c0 = nb * 8 + c_base;
                    float m0 = mrow[c0], m1 = mrow[c0 + 1];
                    float e0 = __expf(cf[i].x) * m0;
                    float e1 = __expf(cf[i].y) * m1;
                    float e2 = __expf(cf[i].z) * m0;
                    float e3 = __expf(cf[i].w) * m1;
                    sum_lo += e0 + e1;
                    sum_hi += e2 + e3;
                    a16[i >> 1][(i & 1) * 2]     = packh2(e0, e1);
                    a16[i >> 1][(i & 1) * 2 + 1] = packh2(e2, e3);
                }
#pragma unroll
                for (int nbo = 0; nbo < 8; nbo++) {
                    uint32_t vaddr = sV[cur] + kb2 * 32 * RSB + nbo * 16 + va_part;
                    uint32_t v0, v1, v2, v3;
                    LDSM4T(v0, v1, v2, v3, vaddr);
                    mma_f16(oc[nbo], a16[0][0], a16[0][1], a16[0][2], a16[0][3], v0, v1);
                    mma_f16(oc[nbo], a16[1][0], a16[1][1], a16[1][2], a16[1][3], v2, v3);
                }
            }

            if (kt + 1 < NTILES) CP_WAIT0();
            __syncthreads();
        }

#pragma unroll
        for (int m = 1; m < 4; m <<= 1) {
            sum_lo += __shfl_xor_sync(0xffffffffu, sum_lo, m);
            sum_hi += __shfl_xor_sync(0xffffffffu, sum_hi, m);
        }
        const float inv_lo = 1.0f / sum_lo;
        const float inv_hi = 1.0f / sum_hi;

        if (q_ == 0) {
            sInv[w * 16 + (L >> 2)]     = inv_lo;
            sInv[w * 16 + 8 + (L >> 2)] = inv_hi;
        }

        // O = O_un * inv
        float* olo = out + ((size_t)bh * S + q0 + w * 16 + (L >> 2)) * D + c_base;
        float* ohi = olo + 8 * D;
#pragma unroll
        for (int nb = 0; nb < 8; nb++) {
            *(float2*)(olo + nb * 8) = make_float2(oc[nb].x * inv_lo, oc[nb].y * inv_lo);
            *(float2*)(ohi + nb * 8) = make_float2(oc[nb].z * inv_hi, oc[nb].w * inv_hi);
        }
    }
    __syncthreads();   // sInv visible; buffers free for pass 2

    // ===== pass 2: attn write (32-row warps, tile-parity split groups) =====
    {
        const int p    = w >> 2;          // tile parity group
        const int g    = w & 3;           // row group: rows 32g..32g+31
        const int gtid = tid & 127;
        const int bar  = 1 + p;
        const uint32_t bufs[2] = { p ? sV[0] : sK[0], p ? sV[1] : sK[1] };

        // Q fragments for the two m-blocks
        uint32_t qa2[2][4][4];
#pragma unroll
        for (int mb = 0; mb < 2; mb++) {
            const uint32_t qb = sQ + (g * 32 + mb * 16) * RSB + q_part;
#pragma unroll
            for (int ks = 0; ks < 4; ks++)
                LDSM4(qa2[mb][ks][0], qa2[mb][ks][1], qa2[mb][ks][2], qa2[mb][ks][3],
                      qb + ks * 32);
        }

        float invA[2], invB[2];
#pragma unroll
        for (int mb = 0; mb < 2; mb++) {
            invA[mb] = sInv[g * 32 + mb * 16 + (L >> 2)];
            invB[mb] = sInv[g * 32 + mb * 16 + 8 + (L >> 2)];
        }
        float* arow0[2];
#pragma unroll
        for (int mb = 0; mb < 2; mb++)
            arow0[mb] = attn + ((size_t)bh * S + q0 + g * 32 + mb * 16 + (L >> 2)) * S;

        load_tile_g(bufs[0], kg + (size_t)p * NT * D, gtid);
        CP_COMMIT();
        CP_WAIT0();
        BARG(bar);

        for (int i = 0; i < 8; i++) {
            const int kt  = p + 2 * i;
            const int cur = i & 1;
            if (i + 1 < 8) {
                load_tile_g(bufs[cur ^ 1], kg + (size_t)(kt + 2) * NT * D, gtid);
                CP_COMMIT();
            }
            const float* mrow = mf + kt * NT;

#pragma unroll
            for (int kb2 = 0; kb2 < 4; kb2++) {
                float4 cf[2][4];
#pragma unroll
                for (int i4 = 0; i4 < 4; i4++) {
                    int nb = kb2 * 4 + i4;
                    uint32_t kaddr = bufs[cur] + nb * 8 * RSB + ka_part;
                    uint32_t b0, b1, b2, b3, b4, b5, b6, b7;
                    LDSM4(b0, b1, b2, b3, kaddr);
                    LDSM4(b4, b5, b6, b7, kaddr + 64);
#pragma unroll
                    for (int mb = 0; mb < 2; mb++) {
                        cf[mb][i4] = make_float4(0.f, 0.f, 0.f, 0.f);
                        mma_f16(cf[mb][i4], qa2[mb][0][0], qa2[mb][0][1], qa2[mb][0][2], qa2[mb][0][3], b0, b1);
                        mma_f16(cf[mb][i4], qa2[mb][1][0], qa2[mb][1][1], qa2[mb][1][2], qa2[mb][1][3], b2, b3);
                        mma_f16(cf[mb][i4], qa2[mb][2][0], qa2[mb][2][1], qa2[mb][2][2], qa2[mb][2][3], b4, b5);
                        mma_f16(cf[mb][i4], qa2[mb][3][0], qa2[mb][3][1], qa2[mb][3][2], qa2[mb][3][3], b6, b7);
                    }
                }
#pragma unroll
                for (int mb = 0; mb < 2; mb++) {
                    float2 flo[4], fhi[4];
#pragma unroll
                    for (int i4 = 0; i4 < 4; i4++) {
                        int c0 = (kb2 * 4 + i4) * 8 + c_base;
                        float m0 = mrow[c0], m1 = mrow[c0 + 1];
                        flo[i4] = make_float2(__expf(cf[mb][i4].x) * m0 * invA[mb],
                                              __expf(cf[mb][i4].y) * m1 * invA[mb]);
                        fhi[i4] = make_float2(__expf(cf[mb][i4].z) * m0 * invB[mb],
                                              __expf(cf[mb][i4].w) * m1 * invB[mb]);
                    }
                    quad_transpose_f2(flo, q_);
                    quad_transpose_f2(fhi, q_);
                    int col = kt * NT + kb2 * 32 + 8 * q_;
                    float* alo = arow0[mb];
                    float* ahi = alo + 8 * (size_t)S;
                    __stcs((float4*)(alo + col),
                           make_float4(flo[0].x, flo[0].y, flo[1].x, flo[1].y));
                    __stcs((float4*)(alo + col + 4),
                           make_float4(flo[2].x, flo[2].y, flo[3].x, flo[3].y));
                    __stcs((float4*)(ahi + col),
                           make_float4(fhi[0].x, fhi[0].y, fhi[1].x, fhi[1].y));
                    __stcs((float4*)(ahi + col + 4),
                           make_float4(fhi[2].x, fhi[2].y, fhi[3].x, fhi[3].y));
                }
            }

            if (i + 1 < 8) CP_WAIT0();
            BARG(bar);
        }
    }
}

// ---------------- launch ----------------
extern "C" void kernel_launch(void* const* d_in, const int* in_sizes, int n_in,
                              void* d_out, int out_size)
{
    const float* q    = (const float*)d_in[0];
    const float* k    = (const float*)d_in[1];
    const float* v    = (const float*)d_in[2];
    const int*   mask = (const int*)  d_in[3];

    float* out  = (float*)d_out;
    float* attn = out + (size_t)BH * S * D;

    cudaFuncSetAttribute(attn_main, cudaFuncAttributeMaxDynamicSharedMemorySize, SMEM_SZ);

    const int N4 = BH * S * D / 4;
    prep16<<<(N4 + 255) / 256, 256>>>(q, k, v);
    attn_main<<<dim3(S / QT, BH), THREADS, SMEM_SZ>>>(mask, out, attn);
}